// round 12
// baseline (speedup 1.0000x reference)
#include <cuda_runtime.h>
#include <cuda_fp16.h>
#include <cstdint>
#include <math.h>

#define BSZ 64
#define TSZ 512
#define ESZ 256
#define USZ 512
#define GSZ 2048
#define NBLK_DIR 16   // scan blocks per direction

// xz layout: [dir][r = t*64+b][gc = u*4+g]  (row-major 2048)
__device__ float  g_xz[(size_t)2 * TSZ * BSZ * GSZ];
__device__ __half g_hf[2][2][(size_t)BSZ * USZ];          // [dir][parity][b*512+u]
__device__ unsigned g_bar_cnt[64];
__device__ unsigned g_bar_gen[64];

// ---- helpers ----
__device__ __forceinline__ uint32_t s2u(const void* p) {
    uint32_t a; asm("{.reg .u64 t; cvta.to.shared.u64 t, %1; cvt.u32.u64 %0, t;}" : "=r"(a) : "l"(p));
    return a;
}
__device__ __forceinline__ void ldsm4(uint32_t& r0, uint32_t& r1, uint32_t& r2, uint32_t& r3, uint32_t a) {
    asm volatile("ldmatrix.sync.aligned.m8n8.x4.shared.b16 {%0,%1,%2,%3}, [%4];"
                 : "=r"(r0), "=r"(r1), "=r"(r2), "=r"(r3) : "r"(a));
}
__device__ __forceinline__ void ldsm4t(uint32_t& r0, uint32_t& r1, uint32_t& r2, uint32_t& r3, uint32_t a) {
    asm volatile("ldmatrix.sync.aligned.m8n8.x4.trans.shared.b16 {%0,%1,%2,%3}, [%4];"
                 : "=r"(r0), "=r"(r1), "=r"(r2), "=r"(r3) : "r"(a));
}
__device__ __forceinline__ void mma16816(float* c, uint32_t a0, uint32_t a1, uint32_t a2, uint32_t a3,
                                         uint32_t b0, uint32_t b1) {
    asm volatile("mma.sync.aligned.m16n8k16.row.col.f32.f16.f16.f32 "
                 "{%0,%1,%2,%3}, {%4,%5,%6,%7}, {%8,%9}, {%0,%1,%2,%3};"
                 : "+f"(c[0]), "+f"(c[1]), "+f"(c[2]), "+f"(c[3])
                 : "r"(a0), "r"(a1), "r"(a2), "r"(a3), "r"(b0), "r"(b1));
}
__device__ __forceinline__ float sigf(float x) { return __fdividef(1.f, 1.f + __expf(-x)); }
__device__ __forceinline__ float tanhf_(float x) { return __fdividef(2.f, 1.f + __expf(-2.f * x)) - 1.f; }

__device__ __forceinline__ void grid_barrier(int dir) {
    __syncthreads();
    if (threadIdx.x == 0) {
        volatile unsigned* gen = &g_bar_gen[dir * 32];
        volatile unsigned* cnt = &g_bar_cnt[dir * 32];
        unsigned g0 = *gen;
        __threadfence();
        unsigned a = atomicAdd(&g_bar_cnt[dir * 32], 1u);
        if (a == NBLK_DIR - 1) {
            *cnt = 0u;
            __threadfence();
            *gen = g0 + 1u;
        } else {
            while (*gen == g0) { }
        }
        __threadfence();
    }
    __syncthreads();
}

// ---------------------------------------------------------------------------
// Kernel 1: HMMA GEMM.  xz[r][gc] = emb[idx] @ W (+bias), fp16 in, fp32 out.
// Block tile 128r x 128gc; 8 warps m32n64; full K=256 in smem.
// ---------------------------------------------------------------------------
#define G1_AS 0            // half [128][264]  -> 67584 B
#define G1_BS 67584        // half [256][136]  -> 69632 B
#define G1_SMEM (67584 + 69632)

__global__ void __launch_bounds__(256) xz_gemm_hmma(
    const int* __restrict__ idx, const float* __restrict__ emb,
    const float* __restrict__ Wf, const float* __restrict__ bf,
    const float* __restrict__ Wb, const float* __restrict__ bb)
{
    extern __shared__ char sm[];
    __shared__ int rowv[128];

    const int dir = blockIdx.z;
    const float* __restrict__ W    = dir ? Wb : Wf;
    const float* __restrict__ bias = dir ? bb : bf;
    float* __restrict__ xzd = g_xz + (size_t)dir * TSZ * BSZ * GSZ;

    const int tid    = threadIdx.x;
    const int rbase  = blockIdx.y * 128;     // rows r = t*64+b
    const int gcbase = blockIdx.x * 128;     // cols gc = u*4+g
    const int ubase  = gcbase >> 2;          // 32 units

    if (tid < 128) {
        int r = rbase + tid;
        rowv[tid] = idx[(r & 63) * TSZ + (r >> 6)];
    }
    __syncthreads();

    // A fill: row lm, half hf -> fp16
    {
        const int lm = tid >> 1, hf = tid & 1;
        const float* ar = emb + (size_t)rowv[lm] * ESZ + hf * 128;
        char* dst = sm + G1_AS + lm * 528 + hf * 256;
#pragma unroll
        for (int j = 0; j < 32; ++j) {
            float4 v = ((const float4*)ar)[j];
            __half2 h01 = __float22half2_rn(make_float2(v.x, v.y));
            __half2 h23 = __float22half2_rn(make_float2(v.z, v.w));
            *(__half2*)(dst + j * 8)     = h01;
            *(__half2*)(dst + j * 8 + 4) = h23;
        }
    }
    // B fill: row k = tid; cols gc = u*4+g (gate-interleaved remap)
    {
        const int k = tid;
        const float* wr = W + (size_t)k * GSZ;
        char* dst = sm + G1_BS + k * 272;
#pragma unroll
        for (int gp = 0; gp < 2; ++gp) {
#pragma unroll
            for (int uq = 0; uq < 8; ++uq) {
                float4 va = *(const float4*)&wr[(2 * gp) * USZ + ubase + uq * 4];
                float4 vb = *(const float4*)&wr[(2 * gp + 1) * USZ + ubase + uq * 4];
                const float* pa = (const float*)&va;
                const float* pb = (const float*)&vb;
#pragma unroll
                for (int i = 0; i < 4; ++i) {
                    __half2 hv = __float22half2_rn(make_float2(pa[i], pb[i]));
                    *(__half2*)(dst + ((uq * 4 + i) * 4 + 2 * gp) * 2) = hv;
                }
            }
        }
    }
    __syncthreads();

    const int w = tid >> 5, l = tid & 31;
    const int mrow = (w & 3) * 32;
    const int ncol = (w >> 2) * 64;
    const uint32_t aB = s2u(sm) + G1_AS + (uint32_t)(mrow + (l & 15)) * 528u + (uint32_t)((l >> 4) * 8) * 2u;
    const uint32_t bB = s2u(sm) + G1_BS + (uint32_t)(l & 15) * 272u + (uint32_t)(ncol + (l >> 4) * 8) * 2u;

    float c[2][8][4];
#pragma unroll
    for (int m = 0; m < 2; ++m)
#pragma unroll
        for (int j = 0; j < 8; ++j)
#pragma unroll
            for (int q = 0; q < 4; ++q) c[m][j][q] = 0.f;

#pragma unroll 4
    for (int k16 = 0; k16 < 16; ++k16) {
        uint32_t a0, a1, a2, a3, a4, a5, a6, a7;
        ldsm4(a0, a1, a2, a3, aB + (uint32_t)k16 * 32u);
        ldsm4(a4, a5, a6, a7, aB + 16u * 528u + (uint32_t)k16 * 32u);
#pragma unroll
        for (int cg = 0; cg < 4; ++cg) {
            uint32_t b0, b1, b2, b3;
            ldsm4t(b0, b1, b2, b3, bB + (uint32_t)k16 * 4352u + (uint32_t)cg * 32u);
            mma16816(c[0][cg * 2],     a0, a1, a2, a3, b0, b1);
            mma16816(c[0][cg * 2 + 1], a0, a1, a2, a3, b2, b3);
            mma16816(c[1][cg * 2],     a4, a5, a6, a7, b0, b1);
            mma16816(c[1][cg * 2 + 1], a4, a5, a6, a7, b2, b3);
        }
    }

    // epilogue: direct row-major float2 stores with bias
    float bv0[8], bv1[8];
#pragma unroll
    for (int j = 0; j < 8; ++j) {
        int gcl = ncol + j * 8 + (l & 3) * 2;
        int gc = gcbase + gcl;
        int g0 = gc & 3, u0 = gc >> 2;
        bv0[j] = bias[g0 * USZ + u0];
        bv1[j] = bias[(g0 + 1) * USZ + u0];
    }
#pragma unroll
    for (int m = 0; m < 2; ++m) {
        int rl = mrow + m * 16 + (l >> 2);
        float* d0 = xzd + (size_t)(rbase + rl) * GSZ + gcbase;
        float* d1 = xzd + (size_t)(rbase + rl + 8) * GSZ + gcbase;
#pragma unroll
        for (int j = 0; j < 8; ++j) {
            int gcl = ncol + j * 8 + (l & 3) * 2;
            *(float2*)(d0 + gcl) = make_float2(c[m][j][0] + bv0[j], c[m][j][1] + bv1[j]);
            *(float2*)(d1 + gcl) = make_float2(c[m][j][2] + bv0[j], c[m][j][3] + bv1[j]);
        }
    }
}

// ---------------------------------------------------------------------------
// Kernel 2: persistent HMMA scan. 32 blocks (16/dir) x 256 thr.
// Block = (dir, 32 units): Z[64b][128gc] = h[64][512] @ U[512][128gc].
// U fp16 resident smem; h staged from global each step; epilogue in
// fragments via shfl; fp32 state in registers (8 cells/thread).
// ---------------------------------------------------------------------------
#define SM_MSK 0
#define SM_AH  4096                 // half [64][520]  -> 66560
#define SM_BU  (4096 + 66560)       // half [512][136] -> 139264
#define SMEM_SCAN (4096 + 66560 + 139264)   // 209920

__global__ void __launch_bounds__(256) lstm_scan_hmma(
    const int* __restrict__ idx,
    const float* __restrict__ Uf, const float* __restrict__ Ub,
    float* __restrict__ out)
{
    extern __shared__ char smem[];
    unsigned long long* msk = (unsigned long long*)(smem + SM_MSK);
    const uint32_t AH = s2u(smem) + SM_AH;
    const uint32_t BU = s2u(smem) + SM_BU;

    const int tid = threadIdx.x;
    const int dir = blockIdx.x >> 4;
    const int ub  = blockIdx.x & 15;                  // 32 units
    const float* __restrict__ Um = dir ? Ub : Uf;
    const float* __restrict__ xzd = g_xz + (size_t)dir * TSZ * BSZ * GSZ;
    __half* __restrict__ hbuf[2] = { g_hf[dir][0], g_hf[dir][1] };

    // one-time: U slice -> fp16 smem [k][gc], gc = ul*4+g, row 272B
    for (int i = tid; i < 512 * 128; i += 256) {
        int k = i >> 7, q = i & 127;
        int g = q >> 5, ul2 = q & 31;
        float v = Um[(size_t)k * GSZ + g * USZ + ub * 32 + ul2];
        *(__half*)(smem + SM_BU + k * 272 + (ul2 * 4 + g) * 2) = __float2half(v);
    }
    // one-time: masks
    for (int tt = tid * 2; tt < tid * 2 + 2; ++tt) {
        unsigned long long m = 0ull;
        for (int b = 0; b < 64; ++b)
            if (idx[b * TSZ + tt] != 0) m |= (1ull << b);
        msk[tt] = m;
    }
    // one-time: zero h parity 0
    {
        uint4 z = { 0u, 0u, 0u, 0u };
        uint4* p = (uint4*)hbuf[0];
#pragma unroll
        for (int j = 0; j < 16; ++j) p[j * 256 + tid] = z;
    }
    grid_barrier(dir);

    // warp coords
    const int w = tid >> 5, l = tid & 31;
    const int mrow = (w & 3) * 16;
    const int ncol = (w >> 2) * 64;
    const uint32_t aB = AH + (uint32_t)(mrow + (l & 15)) * 1040u + (uint32_t)((l >> 4) * 8) * 2u;
    const uint32_t bB = BU + (uint32_t)(l & 15) * 272u + (uint32_t)(ncol + (l >> 4) * 8) * 2u;

    // owned cells: b fixed, 8 units stride 2
    const int b_own = mrow + (l >> 2) + (l & 1) * 8;
    const int ul0 = (ncol >> 2) + ((l >> 1) & 1);     // first owned unit (local)
    float c_st[8], h_st[8];
#pragma unroll
    for (int i = 0; i < 8; ++i) { c_st[i] = 0.f; h_st[i] = 0.f; }

    for (int s = 0; s < TSZ; ++s) {
        const int t = dir ? (TSZ - 1 - s) : s;
        const int cur = s & 1, nxt = cur ^ 1;

        // prefetch xz: 8 owned units x 4 gates (float4 each)
        float4 xv[8];
        {
            const float* xr = xzd + ((size_t)t * BSZ + b_own) * GSZ + ub * 128;
#pragma unroll
            for (int j = 0; j < 8; ++j)
                xv[j] = *(const float4*)(xr + (ul0 + 2 * j) * 4);
        }

        // stage h -> smem A [b][k] fp16 (row 1040B)
        {
            const uint4* src = (const uint4*)hbuf[cur];
#pragma unroll
            for (int j = 0; j < 16; ++j) {
                int cc = j * 256 + tid;
                int bb = cc >> 6, k8 = (cc & 63) * 8;
                *(uint4*)(smem + SM_AH + bb * 1040 + k8 * 2) = src[cc];
            }
        }
        __syncthreads();

        // MMA: 32 k16-iters, warp m16n64
        float c[8][4];
#pragma unroll
        for (int j = 0; j < 8; ++j)
#pragma unroll
            for (int q = 0; q < 4; ++q) c[j][q] = 0.f;
#pragma unroll 8
        for (int k16 = 0; k16 < 32; ++k16) {
            uint32_t a0, a1, a2, a3;
            ldsm4(a0, a1, a2, a3, aB + (uint32_t)k16 * 32u);
#pragma unroll
            for (int cg = 0; cg < 4; ++cg) {
                uint32_t b0, b1, b2, b3;
                ldsm4t(b0, b1, b2, b3, bB + (uint32_t)k16 * 4352u + (uint32_t)cg * 32u);
                mma16816(c[cg * 2],     a0, a1, a2, a3, b0, b1);
                mma16816(c[cg * 2 + 1], a0, a1, a2, a3, b2, b3);
            }
        }

        // epilogue in fragments: exchange within lane pairs, gate math, state
        const bool odd = (l & 1);
        const bool mv = (msk[t] >> b_own) & 1ull;
        __half* hb = hbuf[nxt] + (size_t)b_own * USZ + ub * 32;
        float* ob = out + ((size_t)b_own * TSZ + t) * 1024 + dir * USZ + ub * 32;
#pragma unroll
        for (int j = 0; j < 8; ++j) {
            float s0 = __shfl_xor_sync(0xffffffffu, odd ? c[j][0] : c[j][2], 1);
            float s1 = __shfl_xor_sync(0xffffffffu, odd ? c[j][1] : c[j][3], 1);
            float zi = (odd ? s0 : c[j][0]) + xv[j].x;
            float zf = (odd ? s1 : c[j][1]) + xv[j].y;
            float zg = (odd ? c[j][2] : s0) + xv[j].z;
            float zo = (odd ? c[j][3] : s1) + xv[j].w;
            float ig = sigf(zi), fg = sigf(zf);
            float gg = tanhf_(zg), og = sigf(zo);
            float cn = fg * c_st[j] + ig * gg;
            float hn = og * tanhf_(cn);
            if (mv) { c_st[j] = cn; h_st[j] = hn; }
            int ulj = ul0 + 2 * j;
            ob[ulj] = h_st[j];
            hb[ulj] = __float2half(h_st[j]);
        }
        grid_barrier(dir);
    }

    // final states
    const size_t H0 = (size_t)BSZ * TSZ * 1024;
    const size_t C0 = H0 + (size_t)BSZ * 1024;
#pragma unroll
    for (int j = 0; j < 8; ++j) {
        int u = ub * 32 + ul0 + 2 * j;
        out[H0 + (size_t)b_own * 1024 + dir * USZ + u] = h_st[j];
        out[C0 + (size_t)b_own * 1024 + dir * USZ + u] = c_st[j];
    }
}

// ---------------------------------------------------------------------------
extern "C" void kernel_launch(void* const* d_in, const int* in_sizes, int n_in,
                              void* d_out, int out_size)
{
    const int*   idx = (const int*)  d_in[0];
    const float* emb = (const float*)d_in[1];
    const float* Wf  = (const float*)d_in[2];
    const float* Uf  = (const float*)d_in[3];
    const float* bf  = (const float*)d_in[4];
    const float* Wb  = (const float*)d_in[5];
    const float* Ub  = (const float*)d_in[6];
    const float* bb  = (const float*)d_in[7];
    float* out = (float*)d_out;

    cudaFuncSetAttribute(xz_gemm_hmma,
                         cudaFuncAttributeMaxDynamicSharedMemorySize, G1_SMEM);
    dim3 ggrid(GSZ / 128, (BSZ * TSZ) / 128, 2);
    xz_gemm_hmma<<<ggrid, 256, G1_SMEM>>>(idx, emb, Wf, bf, Wb, bb);

    cudaFuncSetAttribute(lstm_scan_hmma,
                         cudaFuncAttributeMaxDynamicSharedMemorySize, SMEM_SCAN);
    lstm_scan_hmma<<<32, 256, SMEM_SCAN>>>(idx, Uf, Ub, out);
}

// round 13
// speedup vs baseline: 1.2756x; 1.2756x over previous
#include <cuda_runtime.h>
#include <cuda_fp16.h>
#include <cstdint>
#include <math.h>

#define BSZ 64
#define TSZ 512
#define ESZ 256
#define USZ 512
#define GSZ 2048
#define NBLK 128
#define NBLK_DIR 64

// xz layout: [dir][r = t*64+b][gc = u*4+g]
__device__ float  g_xz[(size_t)2 * TSZ * BSZ * GSZ];
__device__ __half g_hf[2][2][(size_t)BSZ * USZ];          // [dir][parity][b*512+u]
__device__ unsigned g_bar_cnt[64];
__device__ unsigned g_bar_gen[64];

// ---- helpers ----
__device__ __forceinline__ uint32_t s2u(const void* p) {
    uint32_t a; asm("{.reg .u64 t; cvta.to.shared.u64 t, %1; cvt.u32.u64 %0, t;}" : "=r"(a) : "l"(p));
    return a;
}
__device__ __forceinline__ void ldsm4(uint32_t& r0, uint32_t& r1, uint32_t& r2, uint32_t& r3, uint32_t a) {
    asm volatile("ldmatrix.sync.aligned.m8n8.x4.shared.b16 {%0,%1,%2,%3}, [%4];"
                 : "=r"(r0), "=r"(r1), "=r"(r2), "=r"(r3) : "r"(a));
}
__device__ __forceinline__ void ldsm4t(uint32_t& r0, uint32_t& r1, uint32_t& r2, uint32_t& r3, uint32_t a) {
    asm volatile("ldmatrix.sync.aligned.m8n8.x4.trans.shared.b16 {%0,%1,%2,%3}, [%4];"
                 : "=r"(r0), "=r"(r1), "=r"(r2), "=r"(r3) : "r"(a));
}
__device__ __forceinline__ void mma16816(float* c, uint32_t a0, uint32_t a1, uint32_t a2, uint32_t a3,
                                         uint32_t b0, uint32_t b1) {
    asm volatile("mma.sync.aligned.m16n8k16.row.col.f32.f16.f16.f32 "
                 "{%0,%1,%2,%3}, {%4,%5,%6,%7}, {%8,%9}, {%0,%1,%2,%3};"
                 : "+f"(c[0]), "+f"(c[1]), "+f"(c[2]), "+f"(c[3])
                 : "r"(a0), "r"(a1), "r"(a2), "r"(a3), "r"(b0), "r"(b1));
}
__device__ __forceinline__ float sigf(float x) { return __fdividef(1.f, 1.f + __expf(-x)); }
__device__ __forceinline__ float tanhf_(float x) { return __fdividef(2.f, 1.f + __expf(-2.f * x)) - 1.f; }

__device__ __forceinline__ void grid_barrier(int dir) {
    __syncthreads();
    if (threadIdx.x == 0) {
        volatile unsigned* gen = &g_bar_gen[dir * 32];
        volatile unsigned* cnt = &g_bar_cnt[dir * 32];
        unsigned g0 = *gen;
        __threadfence();
        unsigned a = atomicAdd(&g_bar_cnt[dir * 32], 1u);
        if (a == NBLK_DIR - 1) {
            *cnt = 0u;
            __threadfence();
            *gen = g0 + 1u;
        } else {
            while (*gen == g0) { }
        }
        __threadfence();
    }
    __syncthreads();
}

// ---------------------------------------------------------------------------
// Kernel 1: HMMA GEMM.  xz[r][gc] = emb[idx] @ W (+bias), fp16 in, fp32 out.
// Block tile 128r x 128gc; 8 warps m32n64; full K=256 in smem.
// ---------------------------------------------------------------------------
#define G1_AS 0            // half [128][264]  -> 67584 B
#define G1_BS 67584        // half [256][136]  -> 69632 B
#define G1_SMEM (67584 + 69632)

__global__ void __launch_bounds__(256) xz_gemm_hmma(
    const int* __restrict__ idx, const float* __restrict__ emb,
    const float* __restrict__ Wf, const float* __restrict__ bf,
    const float* __restrict__ Wb, const float* __restrict__ bb)
{
    extern __shared__ char sm[];
    __shared__ int rowv[128];

    const int dir = blockIdx.z;
    const float* __restrict__ W    = dir ? Wb : Wf;
    const float* __restrict__ bias = dir ? bb : bf;
    float* __restrict__ xzd = g_xz + (size_t)dir * TSZ * BSZ * GSZ;

    const int tid    = threadIdx.x;
    const int rbase  = blockIdx.y * 128;     // rows r = t*64+b
    const int gcbase = blockIdx.x * 128;     // cols gc = u*4+g
    const int ubase  = gcbase >> 2;          // 32 units

    if (tid < 128) {
        int r = rbase + tid;
        rowv[tid] = idx[(r & 63) * TSZ + (r >> 6)];
    }
    __syncthreads();

    // A fill: row lm, half hf -> fp16
    {
        const int lm = tid >> 1, hf = tid & 1;
        const float* ar = emb + (size_t)rowv[lm] * ESZ + hf * 128;
        char* dst = sm + G1_AS + lm * 528 + hf * 256;
#pragma unroll
        for (int j = 0; j < 32; ++j) {
            float4 v = ((const float4*)ar)[j];
            __half2 h01 = __float22half2_rn(make_float2(v.x, v.y));
            __half2 h23 = __float22half2_rn(make_float2(v.z, v.w));
            *(__half2*)(dst + j * 8)     = h01;
            *(__half2*)(dst + j * 8 + 4) = h23;
        }
    }
    // B fill: row k = tid; cols gc = u*4+g (gate-interleaved remap)
    {
        const int k = tid;
        const float* wr = W + (size_t)k * GSZ;
        char* dst = sm + G1_BS + k * 272;
#pragma unroll
        for (int gp = 0; gp < 2; ++gp) {
#pragma unroll
            for (int uq = 0; uq < 8; ++uq) {
                float4 va = *(const float4*)&wr[(2 * gp) * USZ + ubase + uq * 4];
                float4 vb = *(const float4*)&wr[(2 * gp + 1) * USZ + ubase + uq * 4];
                const float* pa = (const float*)&va;
                const float* pb = (const float*)&vb;
#pragma unroll
                for (int i = 0; i < 4; ++i) {
                    __half2 hv = __float22half2_rn(make_float2(pa[i], pb[i]));
                    *(__half2*)(dst + ((uq * 4 + i) * 4 + 2 * gp) * 2) = hv;
                }
            }
        }
    }
    __syncthreads();

    const int w = tid >> 5, l = tid & 31;
    const int mrow = (w & 3) * 32;
    const int ncol = (w >> 2) * 64;
    const uint32_t aB = s2u(sm) + G1_AS + (uint32_t)(mrow + (l & 15)) * 528u + (uint32_t)((l >> 4) * 8) * 2u;
    const uint32_t bB = s2u(sm) + G1_BS + (uint32_t)(l & 15) * 272u + (uint32_t)(ncol + (l >> 4) * 8) * 2u;

    float c[2][8][4];
#pragma unroll
    for (int m = 0; m < 2; ++m)
#pragma unroll
        for (int j = 0; j < 8; ++j)
#pragma unroll
            for (int q = 0; q < 4; ++q) c[m][j][q] = 0.f;

#pragma unroll 4
    for (int k16 = 0; k16 < 16; ++k16) {
        uint32_t a0, a1, a2, a3, a4, a5, a6, a7;
        ldsm4(a0, a1, a2, a3, aB + (uint32_t)k16 * 32u);
        ldsm4(a4, a5, a6, a7, aB + 16u * 528u + (uint32_t)k16 * 32u);
#pragma unroll
        for (int cg = 0; cg < 4; ++cg) {
            uint32_t b0, b1, b2, b3;
            ldsm4t(b0, b1, b2, b3, bB + (uint32_t)k16 * 4352u + (uint32_t)cg * 32u);
            mma16816(c[0][cg * 2],     a0, a1, a2, a3, b0, b1);
            mma16816(c[0][cg * 2 + 1], a0, a1, a2, a3, b2, b3);
            mma16816(c[1][cg * 2],     a4, a5, a6, a7, b0, b1);
            mma16816(c[1][cg * 2 + 1], a4, a5, a6, a7, b2, b3);
        }
    }

    // epilogue: direct row-major float2 stores with bias
    float bv0[8], bv1[8];
#pragma unroll
    for (int j = 0; j < 8; ++j) {
        int gcl = ncol + j * 8 + (l & 3) * 2;
        int gc = gcbase + gcl;
        int g0 = gc & 3, u0 = gc >> 2;
        bv0[j] = bias[g0 * USZ + u0];
        bv1[j] = bias[(g0 + 1) * USZ + u0];
    }
#pragma unroll
    for (int m = 0; m < 2; ++m) {
        int rl = mrow + m * 16 + (l >> 2);
        float* d0 = xzd + (size_t)(rbase + rl) * GSZ + gcbase;
        float* d1 = xzd + (size_t)(rbase + rl + 8) * GSZ + gcbase;
#pragma unroll
        for (int j = 0; j < 8; ++j) {
            int gcl = ncol + j * 8 + (l & 3) * 2;
            *(float2*)(d0 + gcl) = make_float2(c[m][j][0] + bv0[j], c[m][j][1] + bv1[j]);
            *(float2*)(d1 + gcl) = make_float2(c[m][j][2] + bv0[j], c[m][j][3] + bv1[j]);
        }
    }
}

// ---------------------------------------------------------------------------
// Kernel 2: persistent LSTM scan (R11 config: 128 blocks, 8 units/block).
//   Z[b=64][gc=32] = h[b][k=512] @ U[k][gc]
// A = h fp16 smem [64][520], B = U fp16 smem [512][40] (resident).
// 8 warps = 4 M-groups(16b) x 2 N-groups(16gc); 32 k-iters.
// ---------------------------------------------------------------------------
#define SM_MSK 0
#define SM_AH  4096
#define SM_BU  (4096 + 66560)
#define SM_ZS  (4096 + 66560 + 40960)
#define SMEM_SCAN (4096 + 66560 + 40960 + 9216)   // 120832

__global__ void __launch_bounds__(256) lstm_scan_hmma(
    const int* __restrict__ idx,
    const float* __restrict__ Uf, const float* __restrict__ Ub,
    float* __restrict__ out)
{
    extern __shared__ char smem[];
    unsigned long long* msk = (unsigned long long*)(smem + SM_MSK);
    float* Zs = (float*)(smem + SM_ZS);               // [64][36]
    const uint32_t AH = s2u(smem) + SM_AH;
    const uint32_t BU = s2u(smem) + SM_BU;

    const int tid = threadIdx.x;
    const int dir = blockIdx.x >> 6;
    const int ub  = blockIdx.x & 63;                  // 8 units
    const float* __restrict__ Um = dir ? Ub : Uf;
    const float* __restrict__ xzd = g_xz + (size_t)dir * TSZ * BSZ * GSZ;
    __half* __restrict__ hbuf[2] = { g_hf[dir][0], g_hf[dir][1] };

    // one-time: U slice -> fp16 smem [k][gc], gc = ul*4+g, row pad 40 halves
    for (int i = tid; i < 512 * 32; i += 256) {
        int k = i >> 5, gc = i & 31;
        int ul = gc >> 2, g = gc & 3;
        float v = Um[(size_t)k * GSZ + g * USZ + ub * 8 + ul];
        *(__half*)(smem + SM_BU + k * 80 + gc * 2) = __float2half(v);
    }
    // one-time: masks
    for (int tt = tid * 2; tt < tid * 2 + 2; ++tt) {
        unsigned long long m = 0ull;
        for (int b = 0; b < 64; ++b)
            if (idx[b * TSZ + tt] != 0) m |= (1ull << b);
        msk[tt] = m;
    }
    // one-time: zero h parity 0
    {
        uint4 z = { 0u, 0u, 0u, 0u };
        uint4* p = (uint4*)hbuf[0];
#pragma unroll
        for (int j = 0; j < 16; ++j) p[j * 256 + tid] = z;
    }
    grid_barrier(dir);

    // warp MMA coordinates
    const int w = tid >> 5, l = tid & 31;
    const int mrow = (w & 3) * 16;
    const int ncol = (w >> 2) * 16;
    const uint32_t aBase = AH + (uint32_t)(mrow + (l & 15)) * 1040u + (uint32_t)((l >> 4) * 8) * 2u;
    const uint32_t bBase = BU + (uint32_t)(l & 15) * 80u + (uint32_t)(ncol + (l >> 4) * 8) * 2u;

    // owner mapping: 2 cells per thread
    const int b  = tid & 63;
    const int uq = tid >> 6;                          // 0..3
    float c_st[2] = { 0.f, 0.f }, h_st[2] = { 0.f, 0.f };

    for (int s = 0; s < TSZ; ++s) {
        const int t = dir ? (TSZ - 1 - s) : s;
        const int cur = s & 1, nxt = cur ^ 1;

        // prefetch xz: 2 cells, 4 gates contiguous (gc = u*4+g) -> float4 each
        float4 xv[2];
#pragma unroll
        for (int i = 0; i < 2; ++i) {
            int gc0 = (ub * 8 + uq * 2 + i) * 4;
            xv[i] = *(const float4*)&xzd[((size_t)t * BSZ + b) * GSZ + gc0];
        }

        // stage h -> smem A [b][k] fp16, row stride 520 halves
        {
            const uint4* src = (const uint4*)hbuf[cur];
#pragma unroll
            for (int j = 0; j < 16; ++j) {
                int c = j * 256 + tid;
                int bb = c >> 6, u8 = (c & 63) * 8;
                *(uint4*)(smem + SM_AH + bb * 1040 + u8 * 2) = src[c];
            }
        }
        __syncthreads();

        // MMA: 32 k-iters, warp m16n16
        float c0[4] = { 0.f, 0.f, 0.f, 0.f };
        float c1[4] = { 0.f, 0.f, 0.f, 0.f };
#pragma unroll 4
        for (int k0 = 0; k0 < 32; ++k0) {
            uint32_t a0, a1, a2, a3, b0r, b1r, b2r, b3r;
            ldsm4(a0, a1, a2, a3, aBase + (uint32_t)k0 * 32u);
            ldsm4t(b0r, b1r, b2r, b3r, bBase + (uint32_t)k0 * 1280u);
            mma16816(c0, a0, a1, a2, a3, b0r, b1r);
            mma16816(c1, a0, a1, a2, a3, b2r, b3r);
        }

        // dump Z frags -> Zs[64][36]
        {
            int row = mrow + (l >> 2);
            int col = ncol + (l & 3) * 2;
            *(float2*)&Zs[row * 36 + col]           = make_float2(c0[0], c0[1]);
            *(float2*)&Zs[(row + 8) * 36 + col]     = make_float2(c0[2], c0[3]);
            *(float2*)&Zs[row * 36 + col + 8]       = make_float2(c1[0], c1[1]);
            *(float2*)&Zs[(row + 8) * 36 + col + 8] = make_float2(c1[2], c1[3]);
        }
        __syncthreads();

        // epilogue: 2 cells per thread
        const bool mv = (msk[t] >> b) & 1ull;
#pragma unroll
        for (int i = 0; i < 2; ++i) {
            int ul = uq * 2 + i;
            float4 z4 = *(const float4*)&Zs[b * 36 + ul * 4];
            float zi = z4.x + xv[i].x;
            float zf = z4.y + xv[i].y;
            float zg = z4.z + xv[i].z;
            float zo = z4.w + xv[i].w;
            float ig = sigf(zi), fg = sigf(zf);
            float gg = tanhf_(zg), og = sigf(zo);
            float cn = fg * c_st[i] + ig * gg;
            float hn = og * tanhf_(cn);
            if (mv) { c_st[i] = cn; h_st[i] = hn; }
            int u = ub * 8 + ul;
            out[((size_t)b * TSZ + t) * 1024 + dir * USZ + u] = h_st[i];
            hbuf[nxt][(size_t)b * USZ + u] = __float2half(h_st[i]);
        }
        grid_barrier(dir);
    }

    // final states
    const size_t H0 = (size_t)BSZ * TSZ * 1024;
    const size_t C0 = H0 + (size_t)BSZ * 1024;
#pragma unroll
    for (int i = 0; i < 2; ++i) {
        int u = ub * 8 + uq * 2 + i;
        out[H0 + (size_t)b * 1024 + dir * USZ + u] = h_st[i];
        out[C0 + (size_t)b * 1024 + dir * USZ + u] = c_st[i];
    }
}

// ---------------------------------------------------------------------------
extern "C" void kernel_launch(void* const* d_in, const int* in_sizes, int n_in,
                              void* d_out, int out_size)
{
    const int*   idx = (const int*)  d_in[0];
    const float* emb = (const float*)d_in[1];
    const float* Wf  = (const float*)d_in[2];
    const float* Uf  = (const float*)d_in[3];
    const float* bf  = (const float*)d_in[4];
    const float* Wb  = (const float*)d_in[5];
    const float* Ub  = (const float*)d_in[6];
    const float* bb  = (const float*)d_in[7];
    float* out = (float*)d_out;

    cudaFuncSetAttribute(xz_gemm_hmma,
                         cudaFuncAttributeMaxDynamicSharedMemorySize, G1_SMEM);
    dim3 ggrid(GSZ / 128, (BSZ * TSZ) / 128, 2);
    xz_gemm_hmma<<<ggrid, 256, G1_SMEM>>>(idx, emb, Wf, bf, Wb, bb);

    cudaFuncSetAttribute(lstm_scan_hmma,
                         cudaFuncAttributeMaxDynamicSharedMemorySize, SMEM_SCAN);
    lstm_scan_hmma<<<NBLK, 256, SMEM_SCAN>>>(idx, Uf, Ub, out);
}

// round 14
// speedup vs baseline: 1.5220x; 1.1931x over previous
#include <cuda_runtime.h>
#include <cuda_fp16.h>
#include <cstdint>
#include <math.h>

#define BSZ 64
#define TSZ 512
#define ESZ 256
#define USZ 512
#define GSZ 2048
#define NBLK 128
#define NBLK_DIR 64

// xz layout: [dir][r = t*64+b][gc = u*4+g]
__device__ float  g_xz[(size_t)2 * TSZ * BSZ * GSZ];
__device__ __half g_hf[2][2][(size_t)BSZ * USZ];          // [dir][parity][b*512+u]
__device__ unsigned g_bar_cnt[64];                        // [dir*32], monotonic

// ---- helpers ----
__device__ __forceinline__ uint32_t s2u(const void* p) {
    uint32_t a; asm("{.reg .u64 t; cvta.to.shared.u64 t, %1; cvt.u32.u64 %0, t;}" : "=r"(a) : "l"(p));
    return a;
}
__device__ __forceinline__ void ldsm4(uint32_t& r0, uint32_t& r1, uint32_t& r2, uint32_t& r3, uint32_t a) {
    asm volatile("ldmatrix.sync.aligned.m8n8.x4.shared.b16 {%0,%1,%2,%3}, [%4];"
                 : "=r"(r0), "=r"(r1), "=r"(r2), "=r"(r3) : "r"(a));
}
__device__ __forceinline__ void ldsm4t(uint32_t& r0, uint32_t& r1, uint32_t& r2, uint32_t& r3, uint32_t a) {
    asm volatile("ldmatrix.sync.aligned.m8n8.x4.trans.shared.b16 {%0,%1,%2,%3}, [%4];"
                 : "=r"(r0), "=r"(r1), "=r"(r2), "=r"(r3) : "r"(a));
}
__device__ __forceinline__ void mma16816(float* c, uint32_t a0, uint32_t a1, uint32_t a2, uint32_t a3,
                                         uint32_t b0, uint32_t b1) {
    asm volatile("mma.sync.aligned.m16n8k16.row.col.f32.f16.f16.f32 "
                 "{%0,%1,%2,%3}, {%4,%5,%6,%7}, {%8,%9}, {%0,%1,%2,%3};"
                 : "+f"(c[0]), "+f"(c[1]), "+f"(c[2]), "+f"(c[3])
                 : "r"(a0), "r"(a1), "r"(a2), "r"(a3), "r"(b0), "r"(b1));
}
__device__ __forceinline__ float sigf(float x) { return __fdividef(1.f, 1.f + __expf(-x)); }
__device__ __forceinline__ float tanhf_(float x) { return __fdividef(2.f, 1.f + __expf(-2.f * x)) - 1.f; }

// ---------------------------------------------------------------------------
// reset kernel: zero barrier counters (graph-safe, runs before scan each launch)
// ---------------------------------------------------------------------------
__global__ void reset_bar_kernel() {
    if (threadIdx.x < 64) g_bar_cnt[threadIdx.x] = 0u;
}

// ---------------------------------------------------------------------------
// Kernel 1: HMMA GEMM.  xz[r][gc] = emb[idx] @ W (+bias), fp16 in, fp32 out.
// ---------------------------------------------------------------------------
#define G1_AS 0            // half [128][264]  -> 67584 B
#define G1_BS 67584        // half [256][136]  -> 69632 B
#define G1_SMEM (67584 + 69632)

__global__ void __launch_bounds__(256) xz_gemm_hmma(
    const int* __restrict__ idx, const float* __restrict__ emb,
    const float* __restrict__ Wf, const float* __restrict__ bf,
    const float* __restrict__ Wb, const float* __restrict__ bb)
{
    extern __shared__ char sm[];
    __shared__ int rowv[128];

    const int dir = blockIdx.z;
    const float* __restrict__ W    = dir ? Wb : Wf;
    const float* __restrict__ bias = dir ? bb : bf;
    float* __restrict__ xzd = g_xz + (size_t)dir * TSZ * BSZ * GSZ;

    const int tid    = threadIdx.x;
    const int rbase  = blockIdx.y * 128;
    const int gcbase = blockIdx.x * 128;
    const int ubase  = gcbase >> 2;

    if (tid < 128) {
        int r = rbase + tid;
        rowv[tid] = idx[(r & 63) * TSZ + (r >> 6)];
    }
    __syncthreads();

    {
        const int lm = tid >> 1, hf = tid & 1;
        const float* ar = emb + (size_t)rowv[lm] * ESZ + hf * 128;
        char* dst = sm + G1_AS + lm * 528 + hf * 256;
#pragma unroll
        for (int j = 0; j < 32; ++j) {
            float4 v = ((const float4*)ar)[j];
            __half2 h01 = __float22half2_rn(make_float2(v.x, v.y));
            __half2 h23 = __float22half2_rn(make_float2(v.z, v.w));
            *(__half2*)(dst + j * 8)     = h01;
            *(__half2*)(dst + j * 8 + 4) = h23;
        }
    }
    {
        const int k = tid;
        const float* wr = W + (size_t)k * GSZ;
        char* dst = sm + G1_BS + k * 272;
#pragma unroll
        for (int gp = 0; gp < 2; ++gp) {
#pragma unroll
            for (int uq = 0; uq < 8; ++uq) {
                float4 va = *(const float4*)&wr[(2 * gp) * USZ + ubase + uq * 4];
                float4 vb = *(const float4*)&wr[(2 * gp + 1) * USZ + ubase + uq * 4];
                const float* pa = (const float*)&va;
                const float* pb = (const float*)&vb;
#pragma unroll
                for (int i = 0; i < 4; ++i) {
                    __half2 hv = __float22half2_rn(make_float2(pa[i], pb[i]));
                    *(__half2*)(dst + ((uq * 4 + i) * 4 + 2 * gp) * 2) = hv;
                }
            }
        }
    }
    __syncthreads();

    const int w = tid >> 5, l = tid & 31;
    const int mrow = (w & 3) * 32;
    const int ncol = (w >> 2) * 64;
    const uint32_t aB = s2u(sm) + G1_AS + (uint32_t)(mrow + (l & 15)) * 528u + (uint32_t)((l >> 4) * 8) * 2u;
    const uint32_t bB = s2u(sm) + G1_BS + (uint32_t)(l & 15) * 272u + (uint32_t)(ncol + (l >> 4) * 8) * 2u;

    float c[2][8][4];
#pragma unroll
    for (int m = 0; m < 2; ++m)
#pragma unroll
        for (int j = 0; j < 8; ++j)
#pragma unroll
            for (int q = 0; q < 4; ++q) c[m][j][q] = 0.f;

#pragma unroll 4
    for (int k16 = 0; k16 < 16; ++k16) {
        uint32_t a0, a1, a2, a3, a4, a5, a6, a7;
        ldsm4(a0, a1, a2, a3, aB + (uint32_t)k16 * 32u);
        ldsm4(a4, a5, a6, a7, aB + 16u * 528u + (uint32_t)k16 * 32u);
#pragma unroll
        for (int cg = 0; cg < 4; ++cg) {
            uint32_t b0, b1, b2, b3;
            ldsm4t(b0, b1, b2, b3, bB + (uint32_t)k16 * 4352u + (uint32_t)cg * 32u);
            mma16816(c[0][cg * 2],     a0, a1, a2, a3, b0, b1);
            mma16816(c[0][cg * 2 + 1], a0, a1, a2, a3, b2, b3);
            mma16816(c[1][cg * 2],     a4, a5, a6, a7, b0, b1);
            mma16816(c[1][cg * 2 + 1], a4, a5, a6, a7, b2, b3);
        }
    }

    float bv0[8], bv1[8];
#pragma unroll
    for (int j = 0; j < 8; ++j) {
        int gcl = ncol + j * 8 + (l & 3) * 2;
        int gc = gcbase + gcl;
        int g0 = gc & 3, u0 = gc >> 2;
        bv0[j] = bias[g0 * USZ + u0];
        bv1[j] = bias[(g0 + 1) * USZ + u0];
    }
#pragma unroll
    for (int m = 0; m < 2; ++m) {
        int rl = mrow + m * 16 + (l >> 2);
        float* d0 = xzd + (size_t)(rbase + rl) * GSZ + gcbase;
        float* d1 = xzd + (size_t)(rbase + rl + 8) * GSZ + gcbase;
#pragma unroll
        for (int j = 0; j < 8; ++j) {
            int gcl = ncol + j * 8 + (l & 3) * 2;
            *(float2*)(d0 + gcl) = make_float2(c[m][j][0] + bv0[j], c[m][j][1] + bv1[j]);
            *(float2*)(d1 + gcl) = make_float2(c[m][j][2] + bv0[j], c[m][j][3] + bv1[j]);
        }
    }
}

// ---------------------------------------------------------------------------
// Kernel 2: persistent LSTM scan (128 blocks, 8 units/block), RED barrier,
// shfl epilogue, xz prefetch overlapped with barrier wait.
// ---------------------------------------------------------------------------
#define SM_MSK 0
#define SM_AH  4096                       // half [64][520] -> 66560
#define SM_BU  (4096 + 66560)             // half [512][40] -> 40960
#define SMEM_SCAN (4096 + 66560 + 40960)  // 111616

__global__ void __launch_bounds__(256) lstm_scan_hmma(
    const int* __restrict__ idx,
    const float* __restrict__ Uf, const float* __restrict__ Ub,
    float* __restrict__ out)
{
    extern __shared__ char smem[];
    unsigned long long* msk = (unsigned long long*)(smem + SM_MSK);
    const uint32_t AH = s2u(smem) + SM_AH;
    const uint32_t BU = s2u(smem) + SM_BU;

    const int tid = threadIdx.x;
    const int dir = blockIdx.x >> 6;
    const int ub  = blockIdx.x & 63;                  // 8 units
    const float* __restrict__ Um = dir ? Ub : Uf;
    const float* __restrict__ xzd = g_xz + (size_t)dir * TSZ * BSZ * GSZ;
    __half* __restrict__ hbuf[2] = { g_hf[dir][0], g_hf[dir][1] };
    unsigned* const barc = &g_bar_cnt[dir * 32];

    // one-time: U slice -> fp16 smem [k][gc], row pad 40 halves
    for (int i = tid; i < 512 * 32; i += 256) {
        int k = i >> 5, gc = i & 31;
        int ul = gc >> 2, g = gc & 3;
        float v = Um[(size_t)k * GSZ + g * USZ + ub * 8 + ul];
        *(__half*)(smem + SM_BU + k * 80 + gc * 2) = __float2half(v);
    }
    // one-time: masks
    for (int tt = tid * 2; tt < tid * 2 + 2; ++tt) {
        unsigned long long m = 0ull;
        for (int b = 0; b < 64; ++b)
            if (idx[b * TSZ + tt] != 0) m |= (1ull << b);
        msk[tt] = m;
    }
    // one-time: zero h parity 0
    {
        uint4 z = { 0u, 0u, 0u, 0u };
        uint4* p = (uint4*)hbuf[0];
#pragma unroll
        for (int j = 0; j < 16; ++j) p[j * 256 + tid] = z;
    }

    // init barrier
    unsigned target = NBLK_DIR;
    __syncthreads();
    if (tid == 0) {
        __threadfence();
        atomicAdd(barc, 1u);                           // RED (result unused)
        volatile unsigned* vc = barc;
        while (*vc < target) { }
        __threadfence();
    }
    target += NBLK_DIR;
    __syncthreads();

    // warp MMA coordinates
    const int w = tid >> 5, l = tid & 31;
    const int mrow = (w & 3) * 16;
    const int ncol = (w >> 2) * 16;
    const uint32_t aBase = AH + (uint32_t)(mrow + (l & 15)) * 1040u + (uint32_t)((l >> 4) * 8) * 2u;
    const uint32_t bBase = BU + (uint32_t)(l & 15) * 80u + (uint32_t)(ncol + (l >> 4) * 8) * 2u;

    // owner mapping (fragment epilogue): 2 cells per thread
    const int b_own = mrow + (l >> 2) + (l & 1) * 8;
    const int ul0 = (ncol >> 2) + ((l >> 1) & 1);     // units ul0, ul0+2
    float c_st[2] = { 0.f, 0.f }, h_st[2] = { 0.f, 0.f };
    const bool odd = (l & 1);

    // prefetch xz for step 0
    float4 xv[2];
    {
        int t0v = dir ? (TSZ - 1) : 0;
        const float* xr = xzd + ((size_t)t0v * BSZ + b_own) * GSZ + ub * 32;
        xv[0] = *(const float4*)(xr + ul0 * 4);
        xv[1] = *(const float4*)(xr + (ul0 + 2) * 4);
    }

    for (int s = 0; s < TSZ; ++s) {
        const int t = dir ? (TSZ - 1 - s) : s;
        const int cur = s & 1, nxt = cur ^ 1;

        // stage h -> smem A [b][k] fp16 (row 1040 B)
        {
            const uint4* src = (const uint4*)hbuf[cur];
#pragma unroll
            for (int j = 0; j < 16; ++j) {
                int c = j * 256 + tid;
                int bb = c >> 6, u8 = (c & 63) * 8;
                *(uint4*)(smem + SM_AH + bb * 1040 + u8 * 2) = src[c];
            }
        }
        __syncthreads();

        // MMA: 32 k-iters, warp m16n16
        float c0[4] = { 0.f, 0.f, 0.f, 0.f };
        float c1[4] = { 0.f, 0.f, 0.f, 0.f };
#pragma unroll 4
        for (int k0 = 0; k0 < 32; ++k0) {
            uint32_t a0, a1, a2, a3, b0r, b1r, b2r, b3r;
            ldsm4(a0, a1, a2, a3, aBase + (uint32_t)k0 * 32u);
            ldsm4t(b0r, b1r, b2r, b3r, bBase + (uint32_t)k0 * 1280u);
            mma16816(c0, a0, a1, a2, a3, b0r, b1r);
            mma16816(c1, a0, a1, a2, a3, b2r, b3r);
        }

        // epilogue in fragments (shfl gate exchange), update state, store h
        const bool mv = (msk[t] >> b_own) & 1ull;
        float outv[2];
        {
            float* cj[2] = { c0, c1 };
#pragma unroll
            for (int j = 0; j < 2; ++j) {
                float* c = cj[j];
                float s0 = __shfl_xor_sync(0xffffffffu, odd ? c[0] : c[2], 1);
                float s1 = __shfl_xor_sync(0xffffffffu, odd ? c[1] : c[3], 1);
                float zi = (odd ? s0 : c[0]) + xv[j].x;
                float zf = (odd ? s1 : c[1]) + xv[j].y;
                float zg = (odd ? c[2] : s0) + xv[j].z;
                float zo = (odd ? c[3] : s1) + xv[j].w;
                float ig = sigf(zi), fg = sigf(zf);
                float gg = tanhf_(zg), og = sigf(zo);
                float cn = fg * c_st[j] + ig * gg;
                float hn = og * tanhf_(cn);
                if (mv) { c_st[j] = cn; h_st[j] = hn; }
                outv[j] = h_st[j];
                hbuf[nxt][(size_t)b_own * USZ + ub * 8 + ul0 + 2 * j] = __float2half(h_st[j]);
            }
        }
        __syncthreads();
        if (tid == 0) {
            __threadfence();
            atomicAdd(barc, 1u);                       // RED arrival
        }

        // overlapped with other blocks' arrivals: out stores + next xz prefetch
        {
            float* ob = out + ((size_t)b_own * TSZ + t) * 1024 + dir * USZ + ub * 8;
            ob[ul0]     = outv[0];
            ob[ul0 + 2] = outv[1];
        }
        if (s + 1 < TSZ) {
            int tn = dir ? (TSZ - 2 - s) : (s + 1);
            const float* xr = xzd + ((size_t)tn * BSZ + b_own) * GSZ + ub * 32;
            xv[0] = *(const float4*)(xr + ul0 * 4);
            xv[1] = *(const float4*)(xr + (ul0 + 2) * 4);

            if (tid == 0) {
                volatile unsigned* vc = barc;
                while (*vc < target) { }
                __threadfence();
            }
            target += NBLK_DIR;
            __syncthreads();
        }
    }

    // final states
    const size_t H0 = (size_t)BSZ * TSZ * 1024;
    const size_t C0 = H0 + (size_t)BSZ * 1024;
#pragma unroll
    for (int j = 0; j < 2; ++j) {
        int u = ub * 8 + ul0 + 2 * j;
        out[H0 + (size_t)b_own * 1024 + dir * USZ + u] = h_st[j];
        out[C0 + (size_t)b_own * 1024 + dir * USZ + u] = c_st[j];
    }
}

// ---------------------------------------------------------------------------
extern "C" void kernel_launch(void* const* d_in, const int* in_sizes, int n_in,
                              void* d_out, int out_size)
{
    const int*   idx = (const int*)  d_in[0];
    const float* emb = (const float*)d_in[1];
    const float* Wf  = (const float*)d_in[2];
    const float* Uf  = (const float*)d_in[3];
    const float* bf  = (const float*)d_in[4];
    const float* Wb  = (const float*)d_in[5];
    const float* Ub  = (const float*)d_in[6];
    const float* bb  = (const float*)d_in[7];
    float* out = (float*)d_out;

    reset_bar_kernel<<<1, 64>>>();

    cudaFuncSetAttribute(xz_gemm_hmma,
                         cudaFuncAttributeMaxDynamicSharedMemorySize, G1_SMEM);
    dim3 ggrid(GSZ / 128, (BSZ * TSZ) / 128, 2);
    xz_gemm_hmma<<<ggrid, 256, G1_SMEM>>>(idx, emb, Wf, bf, Wb, bb);

    cudaFuncSetAttribute(lstm_scan_hmma,
                         cudaFuncAttributeMaxDynamicSharedMemorySize, SMEM_SCAN);
    lstm_scan_hmma<<<NBLK, 256, SMEM_SCAN>>>(idx, Uf, Ub, out);
}

// round 16
// speedup vs baseline: 2.3701x; 1.5573x over previous
#include <cuda_runtime.h>
#include <cuda_fp16.h>
#include <cstdint>
#include <math.h>

#define BSZ 64
#define TSZ 512
#define ESZ 256
#define USZ 512
#define GSZ 2048
#define NBLK 128
#define FANIN 16      // blocks per sync domain (dir, batch-quarter)

// xz layout: [dir][r = t*64+b][gc = u*4+g]
__device__ float  g_xz[(size_t)2 * TSZ * BSZ * GSZ];
__device__ __half g_hf[2][2][(size_t)BSZ * USZ];          // [dir][parity][b*512+u]
__device__ unsigned g_bar_cnt[256];                       // [domain*32], monotonic

// ---- helpers ----
__device__ __forceinline__ uint32_t s2u(const void* p) {
    uint32_t a; asm("{.reg .u64 t; cvta.to.shared.u64 t, %1; cvt.u32.u64 %0, t;}" : "=r"(a) : "l"(p));
    return a;
}
__device__ __forceinline__ void ldsm4(uint32_t& r0, uint32_t& r1, uint32_t& r2, uint32_t& r3, uint32_t a) {
    asm volatile("ldmatrix.sync.aligned.m8n8.x4.shared.b16 {%0,%1,%2,%3}, [%4];"
                 : "=r"(r0), "=r"(r1), "=r"(r2), "=r"(r3) : "r"(a));
}
__device__ __forceinline__ void ldsm4t(uint32_t& r0, uint32_t& r1, uint32_t& r2, uint32_t& r3, uint32_t a) {
    asm volatile("ldmatrix.sync.aligned.m8n8.x4.trans.shared.b16 {%0,%1,%2,%3}, [%4];"
                 : "=r"(r0), "=r"(r1), "=r"(r2), "=r"(r3) : "r"(a));
}
__device__ __forceinline__ void mma16816(float* c, uint32_t a0, uint32_t a1, uint32_t a2, uint32_t a3,
                                         uint32_t b0, uint32_t b1) {
    asm volatile("mma.sync.aligned.m16n8k16.row.col.f32.f16.f16.f32 "
                 "{%0,%1,%2,%3}, {%4,%5,%6,%7}, {%8,%9}, {%0,%1,%2,%3};"
                 : "+f"(c[0]), "+f"(c[1]), "+f"(c[2]), "+f"(c[3])
                 : "r"(a0), "r"(a1), "r"(a2), "r"(a3), "r"(b0), "r"(b1));
}
__device__ __forceinline__ float sigf(float x) { return __fdividef(1.f, 1.f + __expf(-x)); }
__device__ __forceinline__ float tanhf_(float x) { return __fdividef(2.f, 1.f + __expf(-2.f * x)) - 1.f; }

__global__ void reset_bar_kernel() {
    g_bar_cnt[threadIdx.x] = 0u;
}

// ---------------------------------------------------------------------------
// Kernel 1: HMMA GEMM.  xz[r][gc] = emb[idx] @ W (+bias), fp16 in, fp32 out.
// ---------------------------------------------------------------------------
#define G1_AS 0            // half [128][264]  -> 67584 B
#define G1_BS 67584        // half [256][136]  -> 69632 B
#define G1_SMEM (67584 + 69632)

__global__ void __launch_bounds__(256) xz_gemm_hmma(
    const int* __restrict__ idx, const float* __restrict__ emb,
    const float* __restrict__ Wf, const float* __restrict__ bf,
    const float* __restrict__ Wb, const float* __restrict__ bb)
{
    extern __shared__ char sm[];
    __shared__ int rowv[128];

    const int dir = blockIdx.z;
    const float* __restrict__ W    = dir ? Wb : Wf;
    const float* __restrict__ bias = dir ? bb : bf;
    float* __restrict__ xzd = g_xz + (size_t)dir * TSZ * BSZ * GSZ;

    const int tid    = threadIdx.x;
    const int rbase  = blockIdx.y * 128;
    const int gcbase = blockIdx.x * 128;
    const int ubase  = gcbase >> 2;

    if (tid < 128) {
        int r = rbase + tid;
        rowv[tid] = idx[(r & 63) * TSZ + (r >> 6)];
    }
    __syncthreads();

    {
        const int lm = tid >> 1, hf = tid & 1;
        const float* ar = emb + (size_t)rowv[lm] * ESZ + hf * 128;
        char* dst = sm + G1_AS + lm * 528 + hf * 256;
#pragma unroll
        for (int j = 0; j < 32; ++j) {
            float4 v = ((const float4*)ar)[j];
            __half2 h01 = __float22half2_rn(make_float2(v.x, v.y));
            __half2 h23 = __float22half2_rn(make_float2(v.z, v.w));
            *(__half2*)(dst + j * 8)     = h01;
            *(__half2*)(dst + j * 8 + 4) = h23;
        }
    }
    {
        const int k = tid;
        const float* wr = W + (size_t)k * GSZ;
        char* dst = sm + G1_BS + k * 272;
#pragma unroll
        for (int gp = 0; gp < 2; ++gp) {
#pragma unroll
            for (int uq = 0; uq < 8; ++uq) {
                float4 va = *(const float4*)&wr[(2 * gp) * USZ + ubase + uq * 4];
                float4 vb = *(const float4*)&wr[(2 * gp + 1) * USZ + ubase + uq * 4];
                const float* pa = (const float*)&va;
                const float* pb = (const float*)&vb;
#pragma unroll
                for (int i = 0; i < 4; ++i) {
                    __half2 hv = __float22half2_rn(make_float2(pa[i], pb[i]));
                    *(__half2*)(dst + ((uq * 4 + i) * 4 + 2 * gp) * 2) = hv;
                }
            }
        }
    }
    __syncthreads();

    const int w = tid >> 5, l = tid & 31;
    const int mrow = (w & 3) * 32;
    const int ncol = (w >> 2) * 64;
    const uint32_t aB = s2u(sm) + G1_AS + (uint32_t)(mrow + (l & 15)) * 528u + (uint32_t)((l >> 4) * 8) * 2u;
    const uint32_t bB = s2u(sm) + G1_BS + (uint32_t)(l & 15) * 272u + (uint32_t)(ncol + (l >> 4) * 8) * 2u;

    float c[2][8][4];
#pragma unroll
    for (int m = 0; m < 2; ++m)
#pragma unroll
        for (int j = 0; j < 8; ++j)
#pragma unroll
            for (int q = 0; q < 4; ++q) c[m][j][q] = 0.f;

#pragma unroll 4
    for (int k16 = 0; k16 < 16; ++k16) {
        uint32_t a0, a1, a2, a3, a4, a5, a6, a7;
        ldsm4(a0, a1, a2, a3, aB + (uint32_t)k16 * 32u);
        ldsm4(a4, a5, a6, a7, aB + 16u * 528u + (uint32_t)k16 * 32u);
#pragma unroll
        for (int cg = 0; cg < 4; ++cg) {
            uint32_t b0, b1, b2, b3;
            ldsm4t(b0, b1, b2, b3, bB + (uint32_t)k16 * 4352u + (uint32_t)cg * 32u);
            mma16816(c[0][cg * 2],     a0, a1, a2, a3, b0, b1);
            mma16816(c[0][cg * 2 + 1], a0, a1, a2, a3, b2, b3);
            mma16816(c[1][cg * 2],     a4, a5, a6, a7, b0, b1);
            mma16816(c[1][cg * 2 + 1], a4, a5, a6, a7, b2, b3);
        }
    }

    float bv0[8], bv1[8];
#pragma unroll
    for (int j = 0; j < 8; ++j) {
        int gcl = ncol + j * 8 + (l & 3) * 2;
        int gc = gcbase + gcl;
        int g0 = gc & 3, u0 = gc >> 2;
        bv0[j] = bias[g0 * USZ + u0];
        bv1[j] = bias[(g0 + 1) * USZ + u0];
    }
#pragma unroll
    for (int m = 0; m < 2; ++m) {
        int rl = mrow + m * 16 + (l >> 2);
        float* d0 = xzd + (size_t)(rbase + rl) * GSZ + gcbase;
        float* d1 = xzd + (size_t)(rbase + rl + 8) * GSZ + gcbase;
#pragma unroll
        for (int j = 0; j < 8; ++j) {
            int gcl = ncol + j * 8 + (l & 3) * 2;
            *(float2*)(d0 + gcl) = make_float2(c[m][j][0] + bv0[j], c[m][j][1] + bv1[j]);
            *(float2*)(d1 + gcl) = make_float2(c[m][j][2] + bv0[j], c[m][j][3] + bv1[j]);
        }
    }
}

// ---------------------------------------------------------------------------
// Kernel 2: persistent LSTM scan, 2-D partition (batch-quarter x unit-16th).
// 128 blocks x 256 thr. Block (dir, bq, uj): Z[16b][128gc] = h[16][512] @ U-slice.
// Sync domain = (dir, bq): fan-in 16. U slice resident fp16 smem (139KB);
// h staged 16KB/step; epilogue in fragments via shfl; fp32 state in regs.
// ---------------------------------------------------------------------------
#define SM_MSK 0
#define SM_AH  4096                        // half [16][520]  -> 16640
#define SM_BU  (4096 + 16640)              // half [512][136] -> 139264
#define SMEM_SCAN (4096 + 16640 + 139264)  // 160000

__global__ void __launch_bounds__(256) lstm_scan_hmma(
    const int* __restrict__ idx,
    const float* __restrict__ Uf, const float* __restrict__ Ub,
    float* __restrict__ out)
{
    extern __shared__ char smem[];
    unsigned long long* msk = (unsigned long long*)(smem + SM_MSK);
    const uint32_t AH = s2u(smem) + SM_AH;
    const uint32_t BU = s2u(smem) + SM_BU;

    const int tid = threadIdx.x;
    const int dir = blockIdx.x >> 6;
    const int bq  = (blockIdx.x >> 4) & 3;            // batch quarter (16 batches)
    const int uj  = blockIdx.x & 15;                  // unit 16th (32 units)
    const float* __restrict__ Um = dir ? Ub : Uf;
    const float* __restrict__ xzd = g_xz + (size_t)dir * TSZ * BSZ * GSZ;
    __half* __restrict__ hbuf[2] = { g_hf[dir][0], g_hf[dir][1] };
    unsigned* const barc = &g_bar_cnt[(dir * 4 + bq) * 32];

    // one-time: U slice -> fp16 smem [k][gc], gc = ul*4+g, row 272 B
    for (int i = tid; i < 512 * 128; i += 256) {
        int k = i >> 7, q = i & 127;
        int g = q >> 5, ul2 = q & 31;
        float v = Um[(size_t)k * GSZ + g * USZ + uj * 32 + ul2];
        *(__half*)(smem + SM_BU + k * 272 + (ul2 * 4 + g) * 2) = __float2half(v);
    }
    // one-time: masks
    for (int tt = tid * 2; tt < tid * 2 + 2; ++tt) {
        unsigned long long m = 0ull;
        for (int b = 0; b < 64; ++b)
            if (idx[b * TSZ + tt] != 0) m |= (1ull << b);
        msk[tt] = m;
    }
    // one-time: zero own h stripe (parity 0): 16 b x 32 u = 512 halves
    {
        int r = tid >> 4, u8 = (tid & 15) * 2;        // 16 rows x 16 half2
        *(__half2*)&hbuf[0][(size_t)(bq * 16 + r) * USZ + uj * 32 + u8] =
            __halves2half2(__float2half(0.f), __float2half(0.f));
    }

    // init domain barrier
    unsigned target = FANIN;
    __syncthreads();
    if (tid == 0) {
        __threadfence();
        atomicAdd(barc, 1u);
        volatile unsigned* vc = barc;
        while (*vc < target) { }
        __threadfence();
    }
    target += FANIN;
    __syncthreads();

    // warp MMA coordinates: M=16 (mrow=0), warp n16 at ncol = w*16
    const int w = tid >> 5, l = tid & 31;
    const int ncol = w * 16;
    const uint32_t aBase = AH + (uint32_t)(l & 15) * 1040u + (uint32_t)((l >> 4) * 8) * 2u;
    const uint32_t bBase = BU + (uint32_t)(l & 15) * 272u + (uint32_t)(ncol + (l >> 4) * 8) * 2u;

    // owner mapping (fragment epilogue): 2 cells per thread
    const int b_own = (l >> 2) + (l & 1) * 8;         // 0..15 (local)
    const int ul0 = w * 4 + ((l >> 1) & 1);           // units ul0, ul0+2 (local)
    const int b_glob = bq * 16 + b_own;
    float c_st[2] = { 0.f, 0.f }, h_st[2] = { 0.f, 0.f };
    const bool odd = (l & 1);

    // prefetch xz for step 0
    float4 xv[2];
    {
        int t0v = dir ? (TSZ - 1) : 0;
        const float* xr = xzd + ((size_t)t0v * BSZ + b_glob) * GSZ + uj * 128;
        xv[0] = *(const float4*)(xr + ul0 * 4);
        xv[1] = *(const float4*)(xr + (ul0 + 2) * 4);
    }

    for (int s = 0; s < TSZ; ++s) {
        const int t = dir ? (TSZ - 1 - s) : s;
        const int cur = s & 1, nxt = cur ^ 1;

        // stage h[16 own batches][512] -> smem A (row 1040 B), 1024 uint4
        {
            const uint4* src = (const uint4*)hbuf[cur] + (size_t)bq * 16 * 64;
#pragma unroll
            for (int j = 0; j < 4; ++j) {
                int c = j * 256 + tid;
                int r = c >> 6, k8 = c & 63;
                *(uint4*)(smem + SM_AH + r * 1040 + k8 * 16) = src[r * 64 + k8];
            }
        }
        __syncthreads();

        // MMA: 32 k-iters, warp m16n16
        float c0[4] = { 0.f, 0.f, 0.f, 0.f };
        float c1[4] = { 0.f, 0.f, 0.f, 0.f };
#pragma unroll 4
        for (int k0 = 0; k0 < 32; ++k0) {
            uint32_t a0, a1, a2, a3, b0r, b1r, b2r, b3r;
            ldsm4(a0, a1, a2, a3, aBase + (uint32_t)k0 * 32u);
            ldsm4t(b0r, b1r, b2r, b3r, bBase + (uint32_t)k0 * 4352u);
            mma16816(c0, a0, a1, a2, a3, b0r, b1r);
            mma16816(c1, a0, a1, a2, a3, b2r, b3r);
        }

        // epilogue in fragments (shfl gate exchange), update state, store h
        const bool mv = (msk[t] >> b_glob) & 1ull;
        float outv[2];
        {
            float* cj[2] = { c0, c1 };
#pragma unroll
            for (int j = 0; j < 2; ++j) {
                float* c = cj[j];
                float s0 = __shfl_xor_sync(0xffffffffu, odd ? c[0] : c[2], 1);
                float s1 = __shfl_xor_sync(0xffffffffu, odd ? c[1] : c[3], 1);
                float zi = (odd ? s0 : c[0]) + xv[j].x;
                float zf = (odd ? s1 : c[1]) + xv[j].y;
                float zg = (odd ? c[2] : s0) + xv[j].z;
                float zo = (odd ? c[3] : s1) + xv[j].w;
                float ig = sigf(zi), fg = sigf(zf);
                float gg = tanhf_(zg), og = sigf(zo);
                float cn = fg * c_st[j] + ig * gg;
                float hn = og * tanhf_(cn);
                if (mv) { c_st[j] = cn; h_st[j] = hn; }
                outv[j] = h_st[j];
                hbuf[nxt][(size_t)b_glob * USZ + uj * 32 + ul0 + 2 * j] = __float2half(h_st[j]);
            }
        }
        __syncthreads();
        if (tid == 0) {
            __threadfence();
            atomicAdd(barc, 1u);                       // RED arrival
        }

        // overlapped with other blocks' arrivals: out stores + next xz prefetch
        {
            float* ob = out + ((size_t)b_glob * TSZ + t) * 1024 + dir * USZ + uj * 32;
            ob[ul0]     = outv[0];
            ob[ul0 + 2] = outv[1];
        }
        if (s + 1 < TSZ) {
            int tn = dir ? (TSZ - 2 - s) : (s + 1);
            const float* xr = xzd + ((size_t)tn * BSZ + b_glob) * GSZ + uj * 128;
            xv[0] = *(const float4*)(xr + ul0 * 4);
            xv[1] = *(const float4*)(xr + (ul0 + 2) * 4);

            if (tid == 0) {
                volatile unsigned* vc = barc;
                while (*vc < target) { }
                __threadfence();
            }
            target += FANIN;
            __syncthreads();
        }
    }

    // final states
    const size_t H0 = (size_t)BSZ * TSZ * 1024;
    const size_t C0 = H0 + (size_t)BSZ * 1024;
#pragma unroll
    for (int j = 0; j < 2; ++j) {
        int u = uj * 32 + ul0 + 2 * j;
        out[H0 + (size_t)b_glob * 1024 + dir * USZ + u] = h_st[j];
        out[C0 + (size_t)b_glob * 1024 + dir * USZ + u] = c_st[j];
    }
}

// ---------------------------------------------------------------------------
extern "C" void kernel_launch(void* const* d_in, const int* in_sizes, int n_in,
                              void* d_out, int out_size)
{
    const int*   idx = (const int*)  d_in[0];
    const float* emb = (const float*)d_in[1];
    const float* Wf  = (const float*)d_in[2];
    const float* Uf  = (const float*)d_in[3];
    const float* bf  = (const float*)d_in[4];
    const float* Wb  = (const float*)d_in[5];
    const float* Ub  = (const float*)d_in[6];
    const float* bb  = (const float*)d_in[7];
    float* out = (float*)d_out;

    reset_bar_kernel<<<1, 256>>>();

    cudaFuncSetAttribute(xz_gemm_hmma,
                         cudaFuncAttributeMaxDynamicSharedMemorySize, G1_SMEM);
    dim3 ggrid(GSZ / 128, (BSZ * TSZ) / 128, 2);
    xz_gemm_hmma<<<ggrid, 256, G1_SMEM>>>(idx, emb, Wf, bf, Wb, bb);

    cudaFuncSetAttribute(lstm_scan_hmma,
                         cudaFuncAttributeMaxDynamicSharedMemorySize, SMEM_SCAN);
    lstm_scan_hmma<<<NBLK, 256, SMEM_SCAN>>>(idx, Uf, Ub, out);
}